// round 1
// baseline (speedup 1.0000x reference)
#include <cuda_runtime.h>

// ---------------- problem-size constants ----------------
#define NMAX 50000
#define EMAX 800000
#define F1   64    // hidden dim after W1
#define F2   32    // latent dim after W2
#define DIN  128
#define DOUT 128

// ---------------- device scratch (alloc-free rule: __device__ globals) ----
__device__ float g_deg[NMAX];            // degree, then dinv (in place)
__device__ int   g_src[EMAX];
__device__ int   g_dst[EMAX];
__device__ float g_wn [EMAX];            // dinv[src]*dinv[dst]
__device__ float g_h1[NMAX * F1];        // x @ W1
__device__ float g_a1[NMAX * F1];        // propagated layer-1 (pre bias/relu)
__device__ float g_h2[NMAX * F2];        // relu(a1+b1) @ W2
__device__ float g_a2[NMAX * F2];        // propagated layer-2
__device__ int   g_is64;                 // 1 if edge_index stored as int64

// ---------------- edge-index dtype detection ----------------
// If data is int64 (values in [0,5e4)), every odd 32-bit word is 0.
// If data is int32, odd words are random node ids -> ~surely nonzero.
__global__ void detect_idx_kernel(const int* __restrict__ w, int E) {
    __shared__ int any_nonzero;
    if (threadIdx.x == 0) any_nonzero = 0;
    __syncthreads();
    // sample 256 odd words spread over the buffer (2*E words if int64-sized view is valid either way:
    // buffer has 2*E elements of 4 or 8 bytes; we only touch the first 2*E int32 words, always in-bounds)
    int i = threadIdx.x;
    int stride = (2 * E) / 512;            // stay within first half to be safe for int32 case
    int idx = 2 * (i * stride) + 1;
    if (w[idx] != 0) atomicOr(&any_nonzero, 1);
    __syncthreads();
    if (threadIdx.x == 0) g_is64 = any_nonzero ? 0 : 1;
}

// ---------------- degree / normalization ----------------
__global__ void deg_init_kernel(int n) {
    int i = blockIdx.x * blockDim.x + threadIdx.x;
    if (i < n) g_deg[i] = 1.0f;            // self loop
}

__global__ void deg_count_kernel(const int* __restrict__ w, int E) {
    int e = blockIdx.x * blockDim.x + threadIdx.x;
    if (e >= E) return;
    int d = g_is64 ? w[2 * (E + e)] : w[E + e];
    atomicAdd(&g_deg[d], 1.0f);
}

__global__ void deg_rsqrt_kernel(int n) {
    int i = blockIdx.x * blockDim.x + threadIdx.x;
    if (i < n) g_deg[i] = rsqrtf(g_deg[i]);   // deg >= 1 always (self loop)
}

__global__ void edge_prep_kernel(const int* __restrict__ w, int E) {
    int e = blockIdx.x * blockDim.x + threadIdx.x;
    if (e >= E) return;
    int s, d;
    if (g_is64) { s = w[2 * e]; d = w[2 * (E + e)]; }
    else        { s = w[e];     d = w[E + e];       }
    g_src[e] = s;
    g_dst[e] = d;
    g_wn[e]  = g_deg[s] * g_deg[d];
}

// ---------------- fused GEMM ----------------
// H[node][j] = act(A[node][:]) @ W[:, j]   (+ outb[j] if OBIAS)
// act(v,k)   = INACT ? max(v + ib[k], 0) : v
// if SELF:    G[node][j] = dinv[node]^2 * H[node][j]   (self-loop term of propagation)
template<int KIN, int KOUT, int NR, bool INACT, bool SELF, bool OBIAS>
__global__ void __launch_bounds__(256)
gemm_kernel(const float* __restrict__ A, const float* __restrict__ W,
            const float* __restrict__ ib, const float* __restrict__ ob,
            float* __restrict__ H, float* __restrict__ G, int n)
{
    constexpr int GROUPS = 256 / KOUT;
    constexpr int NPB    = GROUPS * NR;       // nodes per block
    __shared__ float Ws[KIN * KOUT];
    __shared__ float Xs[NPB * KIN];

    const int tid = threadIdx.x;
    for (int idx = tid; idx < KIN * KOUT; idx += 256) Ws[idx] = W[idx];

    const int nb = blockIdx.x * NPB;
    const int valid = min(NPB, n - nb);
    for (int idx = tid; idx < NPB * KIN; idx += 256) {
        int r = idx / KIN;
        float v = 0.0f;
        if (r < valid) {
            v = A[(long long)nb * KIN + idx];
            if (INACT) v = fmaxf(v + ib[idx & (KIN - 1)], 0.0f);
        }
        Xs[idx] = v;
    }
    __syncthreads();

    const int j  = tid % KOUT;
    const int gq = tid / KOUT;
    float acc[NR];
#pragma unroll
    for (int r = 0; r < NR; r++) acc[r] = 0.0f;

#pragma unroll 4
    for (int k = 0; k < KIN; k++) {
        float wv = Ws[k * KOUT + j];
#pragma unroll
        for (int r = 0; r < NR; r++)
            acc[r] += Xs[(gq * NR + r) * KIN + k] * wv;
    }

#pragma unroll
    for (int r = 0; r < NR; r++) {
        int node = nb + gq * NR + r;
        if (node < n) {
            float v = acc[r];
            if (OBIAS) v += ob[j];
            H[(long long)node * KOUT + j] = v;
            if (SELF) {
                float di = g_deg[node];           // holds dinv here
                G[(long long)node * KOUT + j] = di * di * v;
            }
        }
    }
}

// ---------------- edge propagation (scatter-add with vector RED) ----------
// g[dst] += w * h[src], F floats per edge, F/4 lanes per edge, float4 each.
template<int F>
__global__ void __launch_bounds__(256)
prop_kernel(const float* __restrict__ h, float* __restrict__ g, int E)
{
    constexpr int LPE = F / 4;               // lanes per edge (16 or 8)
    constexpr int EPB = 256 / LPE;           // edges per block
    const int tid  = threadIdx.x;
    const int sub  = tid % LPE;
    const int e    = blockIdx.x * EPB + tid / LPE;
    const int lane = tid & 31;
    const int base = lane & ~(LPE - 1);      // leader lane for this edge in the warp

    int s = 0, d = 0; float w = 0.0f;
    if (sub == 0 && e < E) { s = g_src[e]; d = g_dst[e]; w = g_wn[e]; }
    s = __shfl_sync(0xffffffffu, s, base);
    d = __shfl_sync(0xffffffffu, d, base);
    w = __shfl_sync(0xffffffffu, w, base);

    if (e < E) {
        const float4 hv = *reinterpret_cast<const float4*>(h + (long long)s * F + sub * 4);
        float4 m;
        m.x = hv.x * w; m.y = hv.y * w; m.z = hv.z * w; m.w = hv.w * w;
        float* p = g + (long long)d * F + sub * 4;
        asm volatile("red.global.add.v4.f32 [%0], {%1,%2,%3,%4};"
                     :: "l"(p), "f"(m.x), "f"(m.y), "f"(m.z), "f"(m.w)
                     : "memory");
    }
}

// ---------------- launcher ----------------
extern "C" void kernel_launch(void* const* d_in, const int* in_sizes, int n_in,
                              void* d_out, int out_size)
{
    const float* x  = (const float*)d_in[0];
    const int*   ei = (const int*)  d_in[1];   // raw words; dtype detected on device
    const float* W1 = (const float*)d_in[2];
    const float* b1 = (const float*)d_in[3];
    const float* W2 = (const float*)d_in[4];
    const float* b2 = (const float*)d_in[5];
    const float* Wl = (const float*)d_in[6];
    const float* bl = (const float*)d_in[7];
    float* out = (float*)d_out;

    const int n = in_sizes[0] / DIN;     // 50000
    const int E = in_sizes[1] / 2;       // 800000

    void *ph1, *pa1, *ph2, *pa2;
    cudaGetSymbolAddress(&ph1, g_h1);
    cudaGetSymbolAddress(&pa1, g_a1);
    cudaGetSymbolAddress(&ph2, g_h2);
    cudaGetSymbolAddress(&pa2, g_a2);
    float* h1 = (float*)ph1; float* a1 = (float*)pa1;
    float* h2 = (float*)ph2; float* a2 = (float*)pa2;

    // 0. dtype detection + normalization prep
    detect_idx_kernel<<<1, 256>>>(ei, E);
    deg_init_kernel<<<(n + 255) / 256, 256>>>(n);
    deg_count_kernel<<<(E + 255) / 256, 256>>>(ei, E);
    deg_rsqrt_kernel<<<(n + 255) / 256, 256>>>(n);
    edge_prep_kernel<<<(E + 255) / 256, 256>>>(ei, E);

    // 1. h1 = x @ W1 ; a1 = dinv^2 * h1 (self loop)
    {
        constexpr int NPB = (256 / F1) * 8;
        gemm_kernel<DIN, F1, 8, false, true, false>
            <<<(n + NPB - 1) / NPB, 256>>>(x, W1, nullptr, nullptr, h1, a1, n);
    }
    // 2. a1 += sum_edges w * h1[src]
    {
        constexpr int EPB = 256 / (F1 / 4);
        prop_kernel<F1><<<(E + EPB - 1) / EPB, 256>>>(h1, a1, E);
    }
    // 3. h2 = relu(a1 + b1) @ W2 ; a2 = dinv^2 * h2
    {
        constexpr int NPB = (256 / F2) * 8;
        gemm_kernel<F1, F2, 8, true, true, false>
            <<<(n + NPB - 1) / NPB, 256>>>(a1, W2, b1, nullptr, h2, a2, n);
    }
    // 4. a2 += sum_edges w * h2[src]
    {
        constexpr int EPB = 256 / (F2 / 4);
        prop_kernel<F2><<<(E + EPB - 1) / EPB, 256>>>(h2, a2, E);
    }
    // 5. out = relu(a2 + b2) @ Wl + bl
    {
        constexpr int NPB = (256 / DOUT) * 8;
        gemm_kernel<F2, DOUT, 8, true, false, true>
            <<<(n + NPB - 1) / NPB, 256>>>(a2, Wl, b2, bl, out, nullptr, n);
    }
}